// round 4
// baseline (speedup 1.0000x reference)
#include <cuda_runtime.h>
#include <cstdint>

#define NMAX 100000
#define EMAX 1000000
#define HDIM 64
#define PCOLS 256   // NB * H

// ---------------- scratch (device globals; no allocation allowed) ----------------
__device__ float g_h0[(size_t)NMAX * HDIM];
__device__ float g_p[(size_t)NMAX * PCOLS];
__device__ float g_accA[(size_t)NMAX * HDIM];
__device__ float g_accB[(size_t)NMAX * HDIM];
__device__ float g_sum[HDIM];
__device__ int   g_max[HDIM];
// sort scratch
__device__ int g_cnt[NMAX];
__device__ int g_off[NMAX];
__device__ int g_cursor[NMAX];
__device__ int g_bsum[1024];
__device__ unsigned long long g_es[EMAX];   // sorted packed edges: src<<21 | tgt<<4 | et

// ---------------- f32x2 helpers --------------------------------------------------
__device__ __forceinline__ unsigned long long pack2(float lo, float hi) {
    unsigned long long d;
    asm("mov.b64 %0, {%1, %2};" : "=l"(d) : "f"(lo), "f"(hi));
    return d;
}
__device__ __forceinline__ void fma2(unsigned long long& d, unsigned long long a,
                                     unsigned long long b) {
    asm("fma.rn.f32x2 %0, %1, %2, %0;" : "+l"(d) : "l"(a), "l"(b));
}
__device__ __forceinline__ float2 unpack2(unsigned long long d) {
    float2 f;
    asm("mov.b64 {%0, %1}, %2;" : "=f"(f.x), "=f"(f.y) : "l"(d));
    return f;
}

// ---------------- input projection: h0 = x @ W_in + b_in  (N x 15 @ 15 x 64) ----
__global__ __launch_bounds__(256) void input_proj(const float* __restrict__ x,
                                                  const float* __restrict__ Win,
                                                  const float* __restrict__ bin,
                                                  float* __restrict__ h0, int N) {
    __shared__ float sW[15 * 64];
    __shared__ float sx[4][15];
    int tid = threadIdx.x;
    for (int i = tid; i < 15 * 64; i += 256) sW[i] = Win[i];
    int n0 = blockIdx.x * 4;
    if (tid < 60) {
        int r = tid / 15, c = tid % 15;
        int n = n0 + r;
        sx[r][c] = (n < N) ? x[n * 15 + c] : 0.f;
    }
    __syncthreads();
    int r = tid >> 6, j = tid & 63;
    int n = n0 + r;
    if (n < N) {
        float acc = bin[j];
#pragma unroll
        for (int k = 0; k < 15; k++) acc += sx[r][k] * sW[k * 64 + j];
        h0[(size_t)n * 64 + j] = acc;
    }
}

// ---------------- fused RGCN GEMM: [self | p0..p3] = act(A) @ [Wself|B0..B3] -----
// Dynamic smem: As[64][68] + Ws[5][64*64]  (99328 bytes). f32x2 packed math.
__global__ __launch_bounds__(256, 2) void rgcn_fused(const float* __restrict__ A, int relu_in,
                                                     const float* __restrict__ Wself,
                                                     const float* __restrict__ bases,
                                                     const float* __restrict__ bias,
                                                     float* __restrict__ Cself,
                                                     float* __restrict__ P, int N) {
    extern __shared__ float sm[];
    float (*As)[68] = (float(*)[68])sm;
    float* Ws = sm + 64 * 68;
    int tid = threadIdx.x;
    int row0 = blockIdx.x * 64;

#pragma unroll
    for (int i = 0; i < 4; i++) {
        int idx = tid + i * 256;
        int r = idx >> 4, c4 = idx & 15;
        float4 v = make_float4(0.f, 0.f, 0.f, 0.f);
        int n = row0 + r;
        if (n < N) v = *(const float4*)(A + (size_t)n * 64 + c4 * 4);
        if (relu_in) {
            v.x = fmaxf(v.x, 0.f); v.y = fmaxf(v.y, 0.f);
            v.z = fmaxf(v.z, 0.f); v.w = fmaxf(v.w, 0.f);
        }
        *(float4*)(&As[r][c4 * 4]) = v;
    }
#pragma unroll
    for (int i = 0; i < 20; i++) {
        int idx = tid + i * 256;
        float4 v;
        if (idx < 1024) v = *(const float4*)(Wself + idx * 4);
        else            v = *(const float4*)(bases + (size_t)(idx - 1024) * 4);
        *(float4*)(&Ws[idx * 4]) = v;
    }
    __syncthreads();

    int tx = tid & 15, ty = tid >> 4;
    int r0 = ty * 4, c0 = tx * 4;
    unsigned long long acc2[5][8];       // [mat][row*2 + colpair]
#pragma unroll
    for (int m = 0; m < 5; m++)
#pragma unroll
        for (int i = 0; i < 8; i++) acc2[m][i] = 0ull;

#pragma unroll 4
    for (int k = 0; k < 64; k++) {
        float a0 = As[r0 + 0][k], a1 = As[r0 + 1][k];
        float a2 = As[r0 + 2][k], a3 = As[r0 + 3][k];
        unsigned long long A0 = pack2(a0, a0), A1 = pack2(a1, a1);
        unsigned long long A2 = pack2(a2, a2), A3 = pack2(a3, a3);
#pragma unroll
        for (int m = 0; m < 5; m++) {
            ulonglong2 B = *(const ulonglong2*)(&Ws[m * 4096 + k * 64 + c0]);
            fma2(acc2[m][0], A0, B.x); fma2(acc2[m][1], A0, B.y);
            fma2(acc2[m][2], A1, B.x); fma2(acc2[m][3], A1, B.y);
            fma2(acc2[m][4], A2, B.x); fma2(acc2[m][5], A2, B.y);
            fma2(acc2[m][6], A3, B.x); fma2(acc2[m][7], A3, B.y);
        }
    }

    float4 bb = *(const float4*)(bias + c0);
#pragma unroll
    for (int r = 0; r < 4; r++) {
        int n = row0 + r0 + r;
        if (n >= N) continue;
        float2 u0 = unpack2(acc2[0][r * 2]);
        float2 u1 = unpack2(acc2[0][r * 2 + 1]);
        float4 o = make_float4(u0.x + bb.x, u0.y + bb.y, u1.x + bb.z, u1.y + bb.w);
        *(float4*)(Cself + (size_t)n * 64 + c0) = o;
#pragma unroll
        for (int m = 1; m < 5; m++) {
            float2 v0 = unpack2(acc2[m][r * 2]);
            float2 v1 = unpack2(acc2[m][r * 2 + 1]);
            float4 q = make_float4(v0.x, v0.y, v1.x, v1.y);
            *(float4*)(P + (size_t)n * PCOLS + (m - 1) * 64 + c0) = q;
        }
    }
}

// ---------------- generic 64-wide GEMM (node-emb): C = relu(A) @ Wview + b ------
__global__ __launch_bounds__(256) void gemm64(const float* __restrict__ A, int relu_in,
                                              const float* __restrict__ W, int ldW,
                                              const float* __restrict__ bias,
                                              float* __restrict__ C, int ldC, int N) {
    __shared__ float As[64][68];
    __shared__ float Bs[64 * 64];
    int tid = threadIdx.x;
    int row0 = blockIdx.x * 64;
#pragma unroll
    for (int i = 0; i < 4; i++) {
        int idx = tid + i * 256;
        int r = idx >> 4, c4 = idx & 15;
        float4 v = make_float4(0.f, 0.f, 0.f, 0.f);
        int n = row0 + r;
        if (n < N) v = *(const float4*)(A + (size_t)n * 64 + c4 * 4);
        if (relu_in) {
            v.x = fmaxf(v.x, 0.f); v.y = fmaxf(v.y, 0.f);
            v.z = fmaxf(v.z, 0.f); v.w = fmaxf(v.w, 0.f);
        }
        *(float4*)(&As[r][c4 * 4]) = v;
    }
#pragma unroll
    for (int i = 0; i < 4; i++) {
        int idx = tid + i * 256;
        int k = idx >> 4, c4 = idx & 15;
        float4 v = *(const float4*)(W + (size_t)k * ldW + c4 * 4);
        *(float4*)(&Bs[k * 64 + c4 * 4]) = v;
    }
    __syncthreads();

    int tx = tid & 15, ty = tid >> 4;
    int r0 = ty * 4, c0 = tx * 4;
    unsigned long long acc2[8];
#pragma unroll
    for (int i = 0; i < 8; i++) acc2[i] = 0ull;

#pragma unroll 8
    for (int k = 0; k < 64; k++) {
        float a0 = As[r0 + 0][k], a1 = As[r0 + 1][k];
        float a2 = As[r0 + 2][k], a3 = As[r0 + 3][k];
        unsigned long long A0 = pack2(a0, a0), A1 = pack2(a1, a1);
        unsigned long long A2 = pack2(a2, a2), A3 = pack2(a3, a3);
        ulonglong2 B = *(const ulonglong2*)(&Bs[k * 64 + c0]);
        fma2(acc2[0], A0, B.x); fma2(acc2[1], A0, B.y);
        fma2(acc2[2], A1, B.x); fma2(acc2[3], A1, B.y);
        fma2(acc2[4], A2, B.x); fma2(acc2[5], A2, B.y);
        fma2(acc2[6], A3, B.x); fma2(acc2[7], A3, B.y);
    }
    float4 bb = make_float4(0.f, 0.f, 0.f, 0.f);
    if (bias) bb = *(const float4*)(bias + c0);
#pragma unroll
    for (int r = 0; r < 4; r++) {
        int n = row0 + r0 + r;
        if (n >= N) continue;
        float2 u0 = unpack2(acc2[r * 2]);
        float2 u1 = unpack2(acc2[r * 2 + 1]);
        float4 o = make_float4(u0.x + bb.x, u0.y + bb.y, u1.x + bb.z, u1.y + bb.w);
        *(float4*)(C + (size_t)n * ldC + c0) = o;
    }
}

// ---------------- counting sort of edges by src --------------------------------
__global__ void zero_cnt(int* cnt, int N) {
    int i = blockIdx.x * blockDim.x + threadIdx.x;
    if (i < N) cnt[i] = 0;
}
__global__ void hist(const int* __restrict__ src, int* cnt, int E) {
    int e = blockIdx.x * blockDim.x + threadIdx.x;
    if (e < E) atomicAdd(&cnt[src[e]], 1);
}
// warp-shuffle block scan (1024 threads)
__device__ __forceinline__ int block_scan_incl(int v, int* ws) {
    int lane = threadIdx.x & 31, warp = threadIdx.x >> 5;
    int x = v;
#pragma unroll
    for (int d = 1; d < 32; d <<= 1) {
        int t = __shfl_up_sync(0xFFFFFFFFu, x, d);
        if (lane >= d) x += t;
    }
    if (lane == 31) ws[warp] = x;
    __syncthreads();
    if (warp == 0) {
        int y = ws[lane];
#pragma unroll
        for (int d = 1; d < 32; d <<= 1) {
            int t = __shfl_up_sync(0xFFFFFFFFu, y, d);
            if (lane >= d) y += t;
        }
        ws[lane] = y;
    }
    __syncthreads();
    return x + (warp > 0 ? ws[warp - 1] : 0);
}
__global__ __launch_bounds__(1024) void scanA(const int* __restrict__ cnt, int* off,
                                              int* bsum, int N) {
    __shared__ int ws[32];
    int i = blockIdx.x * 1024 + threadIdx.x;
    int v = (i < N) ? cnt[i] : 0;
    int incl = block_scan_incl(v, ws);
    if (i < N) off[i] = incl - v;
    if (threadIdx.x == 1023) bsum[blockIdx.x] = incl;
}
__global__ __launch_bounds__(1024) void scanB(int* bsum, int nchunks) {
    __shared__ int ws[32];
    int v = (threadIdx.x < nchunks) ? bsum[threadIdx.x] : 0;
    int incl = block_scan_incl(v, ws);
    if (threadIdx.x < nchunks) bsum[threadIdx.x] = incl - v;
}
__global__ __launch_bounds__(1024) void scanC(int* off, const int* __restrict__ bsum,
                                              int* cursor, int N) {
    int i = blockIdx.x * 1024 + threadIdx.x;
    if (i < N) {
        int o = off[i] + bsum[blockIdx.x];
        off[i] = o;
        cursor[i] = o;
    }
}
__global__ void permute(const int* __restrict__ src, const int* __restrict__ tgt,
                        const int* __restrict__ et, int* cursor,
                        unsigned long long* es, int E) {
    int e = blockIdx.x * blockDim.x + threadIdx.x;
    if (e < E) {
        int s = src[e];
        int pos = atomicAdd(&cursor[s], 1);
        es[pos] = ((unsigned long long)s << 21) | ((unsigned long long)tgt[e] << 4)
                | (unsigned long long)et[e];
    }
}

// ---------------- edge aggregate: one warp per 64 consecutive sorted edges -------
__global__ __launch_bounds__(256) void edge_agg(const unsigned long long* __restrict__ es,
                                                const float* __restrict__ coeffs,
                                                const float* __restrict__ p,
                                                float* __restrict__ acc, int E) {
    __shared__ unsigned long long se[512];
    __shared__ float4 sc[13];
    int tid = threadIdx.x;
    if (tid < 13) sc[tid] = *(const float4*)(coeffs + tid * 4);
    int base = blockIdx.x * 512;
    for (int i = tid; i < 512; i += 256) {
        int gi = base + i;
        se[i] = (gi < E) ? es[gi] : 0xFFFFFFFFFFFFFFFFull;
    }
    __syncthreads();
    int w = tid >> 5, lane = tid & 31;
    int lo = w * 64;
    int lim = E - base - lo;
    if (lim > 64) lim = 64;
    int cur = -1;
    float2 q0, q1, q2, q3;
    for (int j = 0; j < lim; j++) {
        unsigned long long e = se[lo + j];
        int s = (int)(e >> 21);
        int t = (int)((e >> 4) & 0x1FFFF);
        int r = (int)(e & 15);
        if (s != cur) {
            const float* ps = p + (size_t)s * PCOLS + lane * 2;
            q0 = *(const float2*)(ps);
            q1 = *(const float2*)(ps + 64);
            q2 = *(const float2*)(ps + 128);
            q3 = *(const float2*)(ps + 192);
            cur = s;
        }
        float4 c = sc[r];
        float2 m;
        m.x = c.x * q0.x + c.y * q1.x + c.z * q2.x + c.w * q3.x;
        m.y = c.x * q0.y + c.y * q1.y + c.z * q2.y + c.w * q3.y;
        float* dst = acc + (size_t)t * 64 + lane * 2;
        asm volatile("red.global.add.v2.f32 [%0], {%1,%2};"
                     :: "l"(dst), "f"(m.x), "f"(m.y) : "memory");
    }
}

// ---------------- readout reductions --------------------------------------------
__global__ void zero_stats() {
    int j = threadIdx.x;
    if (j < HDIM) { g_sum[j] = 0.f; g_max[j] = 0; }
}

__global__ __launch_bounds__(256) void reduce_stats(const float* __restrict__ acc, int N) {
    int j = threadIdx.x & 63;
    int rl = threadIdx.x >> 6;
    float s = 0.f, mx = 0.f;
    for (int n = blockIdx.x * 4 + rl; n < N; n += gridDim.x * 4) {
        float v = fmaxf(acc[(size_t)n * 64 + j], 0.f);
        s += v; mx = fmaxf(mx, v);
    }
    __shared__ float ss[4][64];
    __shared__ float smx[4][64];
    ss[rl][j] = s; smx[rl][j] = mx;
    __syncthreads();
    if (rl == 0) {
        s  = ss[0][j] + ss[1][j] + ss[2][j] + ss[3][j];
        mx = fmaxf(fmaxf(smx[0][j], smx[1][j]), fmaxf(smx[2][j], smx[3][j]));
        atomicAdd(&g_sum[j], s);
        atomicMax(&g_max[j], __float_as_int(mx));
    }
}

__global__ void graph_head(const float* __restrict__ Wr1, const float* __restrict__ br1,
                           const float* __restrict__ Wr2, const float* __restrict__ br2,
                           float* __restrict__ out, int N) {
    __shared__ float g[128];
    __shared__ float t[64];
    int tid = threadIdx.x;
    if (tid < 64) g[tid] = g_sum[tid] / (float)N;
    else          g[tid] = __int_as_float(g_max[tid - 64]);
    __syncthreads();
    if (tid < 64) {
        float a = br1[tid];
#pragma unroll 8
        for (int k = 0; k < 128; k++) a += g[k] * Wr1[k * 64 + tid];
        t[tid] = fmaxf(a, 0.f);
    }
    __syncthreads();
    float a = br2[tid];
#pragma unroll 8
    for (int k = 0; k < 64; k++) a += t[k] * Wr2[k * 128 + tid];
    out[tid] = a;
}

// ---------------- launcher -------------------------------------------------------
extern "C" void kernel_launch(void* const* d_in, const int* in_sizes, int n_in,
                              void* d_out, int out_size) {
    const float* x      = (const float*)d_in[0];
    const int*   eidx   = (const int*)  d_in[1];
    const int*   et     = (const int*)  d_in[2];
    const float* Win    = (const float*)d_in[3];
    const float* bin    = (const float*)d_in[4];
    const float* Wself0 = (const float*)d_in[5];
    const float* bself0 = (const float*)d_in[6];
    const float* bases0 = (const float*)d_in[7];
    const float* coef0  = (const float*)d_in[8];
    const float* Wself1 = (const float*)d_in[9];
    const float* bself1 = (const float*)d_in[10];
    const float* bases1 = (const float*)d_in[11];
    const float* coef1  = (const float*)d_in[12];
    const float* Wr1    = (const float*)d_in[13];
    const float* br1    = (const float*)d_in[14];
    const float* Wr2    = (const float*)d_in[15];
    const float* br2    = (const float*)d_in[16];
    const float* Wnp    = (const float*)d_in[17];
    const float* bnp    = (const float*)d_in[18];
    float* out = (float*)d_out;

    int N = in_sizes[0] / 15;
    int E = in_sizes[2];
    const int* src = eidx;
    const int* tgt = eidx + E;

    float *h0, *p, *accA, *accB;
    int *cnt, *off, *cursor, *bsum;
    unsigned long long* es;
    cudaGetSymbolAddress((void**)&h0,     g_h0);
    cudaGetSymbolAddress((void**)&p,      g_p);
    cudaGetSymbolAddress((void**)&accA,   g_accA);
    cudaGetSymbolAddress((void**)&accB,   g_accB);
    cudaGetSymbolAddress((void**)&cnt,    g_cnt);
    cudaGetSymbolAddress((void**)&off,    g_off);
    cudaGetSymbolAddress((void**)&cursor, g_cursor);
    cudaGetSymbolAddress((void**)&bsum,   g_bsum);
    cudaGetSymbolAddress((void**)&es,     g_es);

    const int FUSED_SMEM = (64 * 68 + 5 * 64 * 64) * sizeof(float);   // 99328
    cudaFuncSetAttribute(rgcn_fused, cudaFuncAttributeMaxDynamicSharedMemorySize, FUSED_SMEM);

    int gemm_blocks = (N + 63) / 64;
    int agg_blocks  = (E + 511) / 512;
    int nchunks     = (N + 1023) / 1024;

    // ---- sort edges by src (once; shared by both layers) ----
    zero_cnt<<<(N + 1023) / 1024, 1024>>>(cnt, N);
    hist<<<(E + 255) / 256, 256>>>(src, cnt, E);
    scanA<<<nchunks, 1024>>>(cnt, off, bsum, N);
    scanB<<<1, 1024>>>(bsum, nchunks);
    scanC<<<nchunks, 1024>>>(off, bsum, cursor, N);
    permute<<<(E + 255) / 256, 256>>>(src, tgt, et, cursor, es, E);

    // ---- input projection ----
    input_proj<<<(N + 3) / 4, 256>>>(x, Win, bin, h0, N);

    // ---- layer 0 ----
    rgcn_fused<<<gemm_blocks, 256, FUSED_SMEM>>>(h0, 0, Wself0, bases0, bself0, accA, p, N);
    edge_agg<<<agg_blocks, 256>>>(es, coef0, p, accA, E);

    // ---- layer 1 (input = relu(accA)) ----
    rgcn_fused<<<gemm_blocks, 256, FUSED_SMEM>>>(accA, 1, Wself1, bases1, bself1, accB, p, N);
    edge_agg<<<agg_blocks, 256>>>(es, coef1, p, accB, E);

    // ---- readout (on relu(accB)) ----
    zero_stats<<<1, 64>>>();
    reduce_stats<<<148, 256>>>(accB, N);
    graph_head<<<1, 128>>>(Wr1, br1, Wr2, br2, out, N);

    // ---- node embeddings ----
    for (int half = 0; half < 2; half++)
        gemm64<<<gemm_blocks, 256>>>(accB, 1, Wnp + half * 64, 128, bnp + half * 64,
                                     out + 128 + half * 64, 128, N);
}

// round 5
// speedup vs baseline: 1.5225x; 1.5225x over previous
#include <cuda_runtime.h>
#include <cstdint>

#define NMAX 100000
#define EMAX 1000000
#define HDIM 64
#define PCOLS 256   // NB * H

// ---------------- scratch (device globals; no allocation allowed) ----------------
__device__ float g_h0[(size_t)NMAX * HDIM];
__device__ float g_p[(size_t)NMAX * PCOLS];
__device__ float g_accA[(size_t)NMAX * HDIM];
__device__ float g_accB[(size_t)NMAX * HDIM];
__device__ float g_sum[HDIM];
__device__ int   g_max[HDIM];
// sort scratch
__device__ int g_cnt[NMAX];
__device__ int g_off[NMAX];
__device__ int g_cursor[NMAX];
__device__ int g_bsum[1024];
__device__ unsigned long long g_es[EMAX];   // sorted packed edges: src<<21 | tgt<<4 | et

// ---------------- input projection: h0 = x @ W_in + b_in  (N x 15 @ 15 x 64) ----
__global__ __launch_bounds__(256) void input_proj(const float* __restrict__ x,
                                                  const float* __restrict__ Win,
                                                  const float* __restrict__ bin,
                                                  float* __restrict__ h0, int N) {
    __shared__ float sW[15 * 64];
    __shared__ float sx[4][15];
    int tid = threadIdx.x;
    for (int i = tid; i < 15 * 64; i += 256) sW[i] = Win[i];
    int n0 = blockIdx.x * 4;
    if (tid < 60) {
        int r = tid / 15, c = tid % 15;
        int n = n0 + r;
        sx[r][c] = (n < N) ? x[n * 15 + c] : 0.f;
    }
    __syncthreads();
    int r = tid >> 6, j = tid & 63;
    int n = n0 + r;
    if (n < N) {
        float acc = bin[j];
#pragma unroll
        for (int k = 0; k < 15; k++) acc += sx[r][k] * sW[k * 64 + j];
        h0[(size_t)n * 64 + j] = acc;
    }
}

// ---------------- fused RGCN GEMM: [self | p0..p3] = act(A) @ [Wself|B0..B3] -----
// Dynamic smem: As[64][68] + Ws[5][64*64]  (99328 bytes). Plain FFMA (proven R3).
__global__ __launch_bounds__(256) void rgcn_fused(const float* __restrict__ A, int relu_in,
                                                  const float* __restrict__ Wself,
                                                  const float* __restrict__ bases,
                                                  const float* __restrict__ bias,
                                                  float* __restrict__ Cself,
                                                  float* __restrict__ P, int N) {
    extern __shared__ float sm[];
    float (*As)[68] = (float(*)[68])sm;
    float* Ws = sm + 64 * 68;
    int tid = threadIdx.x;
    int row0 = blockIdx.x * 64;

#pragma unroll
    for (int i = 0; i < 4; i++) {
        int idx = tid + i * 256;
        int r = idx >> 4, c4 = idx & 15;
        float4 v = make_float4(0.f, 0.f, 0.f, 0.f);
        int n = row0 + r;
        if (n < N) v = *(const float4*)(A + (size_t)n * 64 + c4 * 4);
        if (relu_in) {
            v.x = fmaxf(v.x, 0.f); v.y = fmaxf(v.y, 0.f);
            v.z = fmaxf(v.z, 0.f); v.w = fmaxf(v.w, 0.f);
        }
        *(float4*)(&As[r][c4 * 4]) = v;
    }
#pragma unroll
    for (int i = 0; i < 20; i++) {
        int idx = tid + i * 256;
        float4 v;
        if (idx < 1024) v = *(const float4*)(Wself + idx * 4);
        else            v = *(const float4*)(bases + (size_t)(idx - 1024) * 4);
        *(float4*)(&Ws[idx * 4]) = v;
    }
    __syncthreads();

    int tx = tid & 15, ty = tid >> 4;
    int r0 = ty * 4, c0 = tx * 4;
    float acc[5][16];
#pragma unroll
    for (int m = 0; m < 5; m++)
#pragma unroll
        for (int i = 0; i < 16; i++) acc[m][i] = 0.f;

#pragma unroll 4
    for (int k = 0; k < 64; k++) {
        float a0 = As[r0 + 0][k], a1 = As[r0 + 1][k];
        float a2 = As[r0 + 2][k], a3 = As[r0 + 3][k];
#pragma unroll
        for (int m = 0; m < 5; m++) {
            float4 b = *(const float4*)(&Ws[m * 4096 + k * 64 + c0]);
            acc[m][0]  += a0 * b.x; acc[m][1]  += a0 * b.y; acc[m][2]  += a0 * b.z; acc[m][3]  += a0 * b.w;
            acc[m][4]  += a1 * b.x; acc[m][5]  += a1 * b.y; acc[m][6]  += a1 * b.z; acc[m][7]  += a1 * b.w;
            acc[m][8]  += a2 * b.x; acc[m][9]  += a2 * b.y; acc[m][10] += a2 * b.z; acc[m][11] += a2 * b.w;
            acc[m][12] += a3 * b.x; acc[m][13] += a3 * b.y; acc[m][14] += a3 * b.z; acc[m][15] += a3 * b.w;
        }
    }

    float4 bb = *(const float4*)(bias + c0);
#pragma unroll
    for (int r = 0; r < 4; r++) {
        int n = row0 + r0 + r;
        if (n >= N) continue;
        float4 o = make_float4(acc[0][r*4+0] + bb.x, acc[0][r*4+1] + bb.y,
                               acc[0][r*4+2] + bb.z, acc[0][r*4+3] + bb.w);
        *(float4*)(Cself + (size_t)n * 64 + c0) = o;
#pragma unroll
        for (int m = 1; m < 5; m++) {
            float4 q = make_float4(acc[m][r*4+0], acc[m][r*4+1], acc[m][r*4+2], acc[m][r*4+3]);
            *(float4*)(P + (size_t)n * PCOLS + (m - 1) * 64 + c0) = q;
        }
    }
}

// ---------------- generic 64-wide GEMM (node-emb): C = relu(A) @ Wview + b ------
__global__ __launch_bounds__(256) void gemm64(const float* __restrict__ A, int relu_in,
                                              const float* __restrict__ W, int ldW,
                                              const float* __restrict__ bias,
                                              float* __restrict__ C, int ldC, int N) {
    __shared__ float As[64][68];
    __shared__ float Bs[64 * 64];
    int tid = threadIdx.x;
    int row0 = blockIdx.x * 64;
#pragma unroll
    for (int i = 0; i < 4; i++) {
        int idx = tid + i * 256;
        int r = idx >> 4, c4 = idx & 15;
        float4 v = make_float4(0.f, 0.f, 0.f, 0.f);
        int n = row0 + r;
        if (n < N) v = *(const float4*)(A + (size_t)n * 64 + c4 * 4);
        if (relu_in) {
            v.x = fmaxf(v.x, 0.f); v.y = fmaxf(v.y, 0.f);
            v.z = fmaxf(v.z, 0.f); v.w = fmaxf(v.w, 0.f);
        }
        *(float4*)(&As[r][c4 * 4]) = v;
    }
#pragma unroll
    for (int i = 0; i < 4; i++) {
        int idx = tid + i * 256;
        int k = idx >> 4, c4 = idx & 15;
        float4 v = *(const float4*)(W + (size_t)k * ldW + c4 * 4);
        *(float4*)(&Bs[k * 64 + c4 * 4]) = v;
    }
    __syncthreads();

    int tx = tid & 15, ty = tid >> 4;
    int r0 = ty * 4, c0 = tx * 4;
    float acc00=0,acc01=0,acc02=0,acc03=0, acc10=0,acc11=0,acc12=0,acc13=0;
    float acc20=0,acc21=0,acc22=0,acc23=0, acc30=0,acc31=0,acc32=0,acc33=0;
#pragma unroll 16
    for (int k = 0; k < 64; k++) {
        float4 b4 = *(const float4*)(&Bs[k * 64 + c0]);
        float a0 = As[r0 + 0][k], a1 = As[r0 + 1][k];
        float a2 = As[r0 + 2][k], a3 = As[r0 + 3][k];
        acc00 += a0*b4.x; acc01 += a0*b4.y; acc02 += a0*b4.z; acc03 += a0*b4.w;
        acc10 += a1*b4.x; acc11 += a1*b4.y; acc12 += a1*b4.z; acc13 += a1*b4.w;
        acc20 += a2*b4.x; acc21 += a2*b4.y; acc22 += a2*b4.z; acc23 += a2*b4.w;
        acc30 += a3*b4.x; acc31 += a3*b4.y; acc32 += a3*b4.z; acc33 += a3*b4.w;
    }
    float4 bb = make_float4(0.f, 0.f, 0.f, 0.f);
    if (bias) bb = *(const float4*)(bias + c0);
    float4 o;
    int n;
    n = row0 + r0 + 0; if (n < N) { o = make_float4(acc00+bb.x, acc01+bb.y, acc02+bb.z, acc03+bb.w); *(float4*)(C + (size_t)n*ldC + c0) = o; }
    n = row0 + r0 + 1; if (n < N) { o = make_float4(acc10+bb.x, acc11+bb.y, acc12+bb.z, acc13+bb.w); *(float4*)(C + (size_t)n*ldC + c0) = o; }
    n = row0 + r0 + 2; if (n < N) { o = make_float4(acc20+bb.x, acc21+bb.y, acc22+bb.z, acc23+bb.w); *(float4*)(C + (size_t)n*ldC + c0) = o; }
    n = row0 + r0 + 3; if (n < N) { o = make_float4(acc30+bb.x, acc31+bb.y, acc32+bb.z, acc33+bb.w); *(float4*)(C + (size_t)n*ldC + c0) = o; }
}

// ---------------- counting sort of edges by src --------------------------------
__global__ void zero_cnt(int* cnt, int N) {
    int i = blockIdx.x * blockDim.x + threadIdx.x;
    if (i < N) cnt[i] = 0;
}
__global__ void hist(const int* __restrict__ src, int* cnt, int E) {
    int e = blockIdx.x * blockDim.x + threadIdx.x;
    if (e < E) atomicAdd(&cnt[src[e]], 1);
}
// warp-shuffle block scan (1024 threads)
__device__ __forceinline__ int block_scan_incl(int v, int* ws) {
    int lane = threadIdx.x & 31, warp = threadIdx.x >> 5;
    int x = v;
#pragma unroll
    for (int d = 1; d < 32; d <<= 1) {
        int t = __shfl_up_sync(0xFFFFFFFFu, x, d);
        if (lane >= d) x += t;
    }
    if (lane == 31) ws[warp] = x;
    __syncthreads();
    if (warp == 0) {
        int y = ws[lane];
#pragma unroll
        for (int d = 1; d < 32; d <<= 1) {
            int t = __shfl_up_sync(0xFFFFFFFFu, y, d);
            if (lane >= d) y += t;
        }
        ws[lane] = y;
    }
    __syncthreads();
    return x + (warp > 0 ? ws[warp - 1] : 0);
}
__global__ __launch_bounds__(1024) void scanA(const int* __restrict__ cnt, int* off,
                                              int* bsum, int N) {
    __shared__ int ws[32];
    int i = blockIdx.x * 1024 + threadIdx.x;
    int v = (i < N) ? cnt[i] : 0;
    int incl = block_scan_incl(v, ws);
    if (i < N) off[i] = incl - v;
    if (threadIdx.x == 1023) bsum[blockIdx.x] = incl;
}
__global__ __launch_bounds__(1024) void scanB(int* bsum, int nchunks) {
    __shared__ int ws[32];
    int v = (threadIdx.x < nchunks) ? bsum[threadIdx.x] : 0;
    int incl = block_scan_incl(v, ws);
    if (threadIdx.x < nchunks) bsum[threadIdx.x] = incl - v;
}
__global__ __launch_bounds__(1024) void scanC(int* off, const int* __restrict__ bsum,
                                              int* cursor, int N) {
    int i = blockIdx.x * 1024 + threadIdx.x;
    if (i < N) {
        int o = off[i] + bsum[blockIdx.x];
        off[i] = o;
        cursor[i] = o;
    }
}
__global__ void permute(const int* __restrict__ src, const int* __restrict__ tgt,
                        const int* __restrict__ et, int* cursor,
                        unsigned long long* es, int E) {
    int e = blockIdx.x * blockDim.x + threadIdx.x;
    if (e < E) {
        int s = src[e];
        int pos = atomicAdd(&cursor[s], 1);
        es[pos] = ((unsigned long long)s << 21) | ((unsigned long long)tgt[e] << 4)
                | (unsigned long long)et[e];
    }
}

// ---------------- edge aggregate: one full warp per source node ------------------
// Warp loads p[node] row once into registers (8 floats/lane), then streams that
// node's sorted edges with next-edge prefetch; one red.v2 per lane per edge.
__global__ __launch_bounds__(256) void edge_agg(const int* __restrict__ off,
                                                const unsigned long long* __restrict__ es,
                                                const float* __restrict__ coeffs,
                                                const float* __restrict__ p,
                                                float* __restrict__ acc, int N, int E) {
    int g = blockIdx.x * 8 + (threadIdx.x >> 5);
    int lane = threadIdx.x & 31;
    if (g >= N) return;
    int beg = off[g];
    int end = (g + 1 < N) ? off[g + 1] : E;
    if (beg == end) return;

    const float* ps = p + (size_t)g * PCOLS + lane * 2;
    float2 q0 = *(const float2*)(ps);
    float2 q1 = *(const float2*)(ps + 64);
    float2 q2 = *(const float2*)(ps + 128);
    float2 q3 = *(const float2*)(ps + 192);

    unsigned long long e = es[beg];
    for (int i = beg; i < end; i++) {
        unsigned long long enx = (i + 1 < end) ? es[i + 1] : 0ull;   // prefetch
        int t = (int)((e >> 4) & 0x1FFFF);
        int r = (int)(e & 15);
        float4 c = *(const float4*)(coeffs + r * 4);
        float2 m;
        m.x = c.x * q0.x + c.y * q1.x + c.z * q2.x + c.w * q3.x;
        m.y = c.x * q0.y + c.y * q1.y + c.z * q2.y + c.w * q3.y;
        float* dst = acc + (size_t)t * 64 + lane * 2;
        asm volatile("red.global.add.v2.f32 [%0], {%1,%2};"
                     :: "l"(dst), "f"(m.x), "f"(m.y) : "memory");
        e = enx;
    }
}

// ---------------- readout reductions --------------------------------------------
__global__ void zero_stats() {
    int j = threadIdx.x;
    if (j < HDIM) { g_sum[j] = 0.f; g_max[j] = 0; }
}

__global__ __launch_bounds__(256) void reduce_stats(const float* __restrict__ acc, int N) {
    int j = threadIdx.x & 63;
    int rl = threadIdx.x >> 6;
    float s = 0.f, mx = 0.f;
    for (int n = blockIdx.x * 4 + rl; n < N; n += gridDim.x * 4) {
        float v = fmaxf(acc[(size_t)n * 64 + j], 0.f);
        s += v; mx = fmaxf(mx, v);
    }
    __shared__ float ss[4][64];
    __shared__ float smx[4][64];
    ss[rl][j] = s; smx[rl][j] = mx;
    __syncthreads();
    if (rl == 0) {
        s  = ss[0][j] + ss[1][j] + ss[2][j] + ss[3][j];
        mx = fmaxf(fmaxf(smx[0][j], smx[1][j]), fmaxf(smx[2][j], smx[3][j]));
        atomicAdd(&g_sum[j], s);
        atomicMax(&g_max[j], __float_as_int(mx));
    }
}

__global__ void graph_head(const float* __restrict__ Wr1, const float* __restrict__ br1,
                           const float* __restrict__ Wr2, const float* __restrict__ br2,
                           float* __restrict__ out, int N) {
    __shared__ float g[128];
    __shared__ float t[64];
    int tid = threadIdx.x;
    if (tid < 64) g[tid] = g_sum[tid] / (float)N;
    else          g[tid] = __int_as_float(g_max[tid - 64]);
    __syncthreads();
    if (tid < 64) {
        float a = br1[tid];
#pragma unroll 8
        for (int k = 0; k < 128; k++) a += g[k] * Wr1[k * 64 + tid];
        t[tid] = fmaxf(a, 0.f);
    }
    __syncthreads();
    float a = br2[tid];
#pragma unroll 8
    for (int k = 0; k < 64; k++) a += t[k] * Wr2[k * 128 + tid];
    out[tid] = a;
}

// ---------------- launcher -------------------------------------------------------
extern "C" void kernel_launch(void* const* d_in, const int* in_sizes, int n_in,
                              void* d_out, int out_size) {
    const float* x      = (const float*)d_in[0];
    const int*   eidx   = (const int*)  d_in[1];
    const int*   et     = (const int*)  d_in[2];
    const float* Win    = (const float*)d_in[3];
    const float* bin    = (const float*)d_in[4];
    const float* Wself0 = (const float*)d_in[5];
    const float* bself0 = (const float*)d_in[6];
    const float* bases0 = (const float*)d_in[7];
    const float* coef0  = (const float*)d_in[8];
    const float* Wself1 = (const float*)d_in[9];
    const float* bself1 = (const float*)d_in[10];
    const float* bases1 = (const float*)d_in[11];
    const float* coef1  = (const float*)d_in[12];
    const float* Wr1    = (const float*)d_in[13];
    const float* br1    = (const float*)d_in[14];
    const float* Wr2    = (const float*)d_in[15];
    const float* br2    = (const float*)d_in[16];
    const float* Wnp    = (const float*)d_in[17];
    const float* bnp    = (const float*)d_in[18];
    float* out = (float*)d_out;

    int N = in_sizes[0] / 15;
    int E = in_sizes[2];
    const int* src = eidx;
    const int* tgt = eidx + E;

    float *h0, *p, *accA, *accB;
    int *cnt, *off, *cursor, *bsum;
    unsigned long long* es;
    cudaGetSymbolAddress((void**)&h0,     g_h0);
    cudaGetSymbolAddress((void**)&p,      g_p);
    cudaGetSymbolAddress((void**)&accA,   g_accA);
    cudaGetSymbolAddress((void**)&accB,   g_accB);
    cudaGetSymbolAddress((void**)&cnt,    g_cnt);
    cudaGetSymbolAddress((void**)&off,    g_off);
    cudaGetSymbolAddress((void**)&cursor, g_cursor);
    cudaGetSymbolAddress((void**)&bsum,   g_bsum);
    cudaGetSymbolAddress((void**)&es,     g_es);

    const int FUSED_SMEM = (64 * 68 + 5 * 64 * 64) * sizeof(float);   // 99328
    cudaFuncSetAttribute(rgcn_fused, cudaFuncAttributeMaxDynamicSharedMemorySize, FUSED_SMEM);

    int gemm_blocks = (N + 63) / 64;
    int agg_blocks  = (N + 7) / 8;
    int nchunks     = (N + 1023) / 1024;

    // ---- sort edges by src (once; shared by both layers) ----
    zero_cnt<<<(N + 1023) / 1024, 1024>>>(cnt, N);
    hist<<<(E + 255) / 256, 256>>>(src, cnt, E);
    scanA<<<nchunks, 1024>>>(cnt, off, bsum, N);
    scanB<<<1, 1024>>>(bsum, nchunks);
    scanC<<<nchunks, 1024>>>(off, bsum, cursor, N);
    permute<<<(E + 255) / 256, 256>>>(src, tgt, et, cursor, es, E);

    // ---- input projection ----
    input_proj<<<(N + 3) / 4, 256>>>(x, Win, bin, h0, N);

    // ---- layer 0 ----
    rgcn_fused<<<gemm_blocks, 256, FUSED_SMEM>>>(h0, 0, Wself0, bases0, bself0, accA, p, N);
    edge_agg<<<agg_blocks, 256>>>(off, es, coef0, p, accA, N, E);

    // ---- layer 1 (input = relu(accA)) ----
    rgcn_fused<<<gemm_blocks, 256, FUSED_SMEM>>>(accA, 1, Wself1, bases1, bself1, accB, p, N);
    edge_agg<<<agg_blocks, 256>>>(off, es, coef1, p, accB, N, E);

    // ---- readout (on relu(accB)) ----
    zero_stats<<<1, 64>>>();
    reduce_stats<<<148, 256>>>(accB, N);
    graph_head<<<1, 128>>>(Wr1, br1, Wr2, br2, out, N);

    // ---- node embeddings ----
    for (int half = 0; half < 2; half++)
        gemm64<<<gemm_blocks, 256>>>(accB, 1, Wnp + half * 64, 128, bnp + half * 64,
                                     out + 128 + half * 64, 128, N);
}

// round 17
// speedup vs baseline: 1.9220x; 1.2624x over previous
#include <cuda_runtime.h>
#include <cstdint>

#define NMAX 100000
#define EMAX 1000000
#define HDIM 64
#define PCOLS 256   // NB * H

// ---------------- scratch (device globals; no allocation allowed) ----------------
// Note: h0 aliases g_accB (disjoint lifetimes: h0 dead after layer-0 GEMM reads it;
// accB first written by layer-1 GEMM). cursor aliases g_cnt (counts dead after scanA).
__device__ float g_p[(size_t)NMAX * PCOLS];
__device__ float g_accA[(size_t)NMAX * HDIM];
__device__ float g_accB[(size_t)NMAX * HDIM];
__device__ float g_sum[HDIM];
__device__ int   g_max[HDIM];
// sort scratch
__device__ int g_cnt[NMAX];
__device__ int g_off[NMAX];
__device__ int g_bsum[1024];
__device__ unsigned long long g_es[EMAX];   // sorted packed edges: src<<21 | tgt<<4 | et

// ---------------- input projection: h0 = x @ W_in + b_in ------------------------
__global__ __launch_bounds__(256) void input_proj(const float* __restrict__ x,
                                                  const float* __restrict__ Win,
                                                  const float* __restrict__ bin,
                                                  float* __restrict__ h0, int N) {
    __shared__ float sW[15 * 64];
    __shared__ float sx[4][15];
    int tid = threadIdx.x;
    for (int i = tid; i < 15 * 64; i += 256) sW[i] = Win[i];
    int n0 = blockIdx.x * 4;
    if (tid < 60) {
        int r = tid / 15, c = tid % 15;
        int n = n0 + r;
        sx[r][c] = (n < N) ? x[n * 15 + c] : 0.f;
    }
    __syncthreads();
    int r = tid >> 6, j = tid & 63;
    int n = n0 + r;
    if (n < N) {
        float acc = bin[j];
#pragma unroll
        for (int k = 0; k < 15; k++) acc += sx[r][k] * sW[k * 64 + j];
        h0[(size_t)n * 64 + j] = acc;
    }
}

// ================= generic tf32 mma.sync GEMM ===================================
// C[N x nch*64] = act(A[N x 64]) @ [W0 chunks | W1] with per-chunk output routing.
// SMEM: As[128][68] + Ws[nch][64][68] (transposed [n][k]) + bias[128].
#define MM_AS     (128 * 68)                 // floats
#define MM_WCH    (64 * 68)
#define MM_SMEM   ((MM_AS + 5 * MM_WCH + 128) * 4)

__device__ __forceinline__ float to_tf32(float x) {
    float y; asm("cvt.rna.tf32.f32 %0, %1;" : "=f"(y) : "f"(x)); return y;
}

__global__ void __launch_bounds__(256, 1)
mma_gemm(const float* __restrict__ A, int relu_in,
         const float* __restrict__ W0, int w0ld, int w0stride, int w0chunks,
         const float* __restrict__ W1,
         const float* __restrict__ bias, int bias_all, int nbias,
         float* __restrict__ dst0, int ld0, float* __restrict__ dst1,
         int N, int ntiles) {
    extern __shared__ float sm[];
    float (*As)[68] = (float(*)[68])sm;
    float* Ws = sm + MM_AS;
    float* bias_sm = Ws + 5 * MM_WCH;
    int tid = threadIdx.x;
    int nch = w0chunks + (W1 != nullptr ? 1 : 0);

    // Load weight chunks transposed ([n][k], stride 68), tf32-rounded
    for (int idx = tid; idx < w0chunks * 4096; idx += 256) {
        int m = idx >> 12, k = (idx >> 6) & 63, n = idx & 63;
        Ws[m * MM_WCH + n * 68 + k] = to_tf32(W0[(size_t)m * w0stride + k * w0ld + n]);
    }
    if (W1) {
        for (int idx = tid; idx < 4096; idx += 256) {
            int k = idx >> 6, n = idx & 63;
            Ws[w0chunks * MM_WCH + n * 68 + k] = to_tf32(W1[k * 64 + n]);
        }
    }
    if (tid < nbias) bias_sm[tid] = bias[tid];
    __syncthreads();

    int warp = tid >> 5, lane = tid & 31;
    int grp = lane >> 2, tig = lane & 3;
    int r0 = warp * 16;

    for (int tile = blockIdx.x; tile < ntiles; tile += gridDim.x) {
        int row0 = tile * 128;
        __syncthreads();   // previous iteration's A-fragment reads complete
        // stage A tile (tf32-rounded, optional relu, zero-pad tail)
        for (int idx = tid; idx < 2048; idx += 256) {
            int r = idx >> 4, c4 = idx & 15;
            int n = row0 + r;
            float4 v = make_float4(0.f, 0.f, 0.f, 0.f);
            if (n < N) v = *(const float4*)(A + (size_t)n * 64 + c4 * 4);
            if (relu_in) {
                v.x = fmaxf(v.x, 0.f); v.y = fmaxf(v.y, 0.f);
                v.z = fmaxf(v.z, 0.f); v.w = fmaxf(v.w, 0.f);
            }
            v.x = to_tf32(v.x); v.y = to_tf32(v.y);
            v.z = to_tf32(v.z); v.w = to_tf32(v.w);
            *(float4*)(&As[r][c4 * 4]) = v;
        }
        __syncthreads();

        // A fragments for this warp's 16 rows (kept across all chunks)
        uint32_t afr[8][4];
#pragma unroll
        for (int k8 = 0; k8 < 8; k8++) {
            afr[k8][0] = __float_as_uint(As[r0 + grp][k8 * 8 + tig]);
            afr[k8][1] = __float_as_uint(As[r0 + grp + 8][k8 * 8 + tig]);
            afr[k8][2] = __float_as_uint(As[r0 + grp][k8 * 8 + tig + 4]);
            afr[k8][3] = __float_as_uint(As[r0 + grp + 8][k8 * 8 + tig + 4]);
        }

        int rA = row0 + r0 + grp, rB = rA + 8;
        for (int m = 0; m < nch; m++) {
            float c[8][4];
#pragma unroll
            for (int i = 0; i < 8; i++) { c[i][0] = 0.f; c[i][1] = 0.f; c[i][2] = 0.f; c[i][3] = 0.f; }
            const float* wm = Ws + m * MM_WCH;
#pragma unroll
            for (int k8 = 0; k8 < 8; k8++) {
#pragma unroll
                for (int n8 = 0; n8 < 8; n8++) {
                    uint32_t b0 = __float_as_uint(wm[(n8 * 8 + grp) * 68 + k8 * 8 + tig]);
                    uint32_t b1 = __float_as_uint(wm[(n8 * 8 + grp) * 68 + k8 * 8 + tig + 4]);
                    asm volatile(
                        "mma.sync.aligned.m16n8k8.row.col.f32.tf32.tf32.f32 "
                        "{%0,%1,%2,%3}, {%4,%5,%6,%7}, {%8,%9}, {%0,%1,%2,%3};"
                        : "+f"(c[n8][0]), "+f"(c[n8][1]), "+f"(c[n8][2]), "+f"(c[n8][3])
                        : "r"(afr[k8][0]), "r"(afr[k8][1]), "r"(afr[k8][2]), "r"(afr[k8][3]),
                          "r"(b0), "r"(b1));
                }
            }
            // epilogue for this chunk
            bool last = (dst1 != nullptr) && (m == nch - 1);
            float* base = last ? dst1 : dst0 + m * 64;
            int ld = last ? 64 : ld0;
            int boff = last ? 0 : m * 64;
            int usebias = last || bias_all;
#pragma unroll
            for (int n8 = 0; n8 < 8; n8++) {
                int col = n8 * 8 + tig * 2;
                float bx = 0.f, by = 0.f;
                if (usebias) { bx = bias_sm[boff + col]; by = bias_sm[boff + col + 1]; }
                if (rA < N) *(float2*)(base + (size_t)rA * ld + col)
                    = make_float2(c[n8][0] + bx, c[n8][1] + by);
                if (rB < N) *(float2*)(base + (size_t)rB * ld + col)
                    = make_float2(c[n8][2] + bx, c[n8][3] + by);
            }
        }
    }
}

// ---------------- counting sort of edges by src --------------------------------
__global__ void zero_cnt(int* cnt, int N) {
    int i = blockIdx.x * blockDim.x + threadIdx.x;
    if (i < N) cnt[i] = 0;
}
__global__ void hist(const int* __restrict__ src, int* cnt, int E) {
    int e = blockIdx.x * blockDim.x + threadIdx.x;
    if (e < E) atomicAdd(&cnt[src[e]], 1);
}
__device__ __forceinline__ int block_scan_incl(int v, int* ws) {
    int lane = threadIdx.x & 31, warp = threadIdx.x >> 5;
    int x = v;
#pragma unroll
    for (int d = 1; d < 32; d <<= 1) {
        int t = __shfl_up_sync(0xFFFFFFFFu, x, d);
        if (lane >= d) x += t;
    }
    if (lane == 31) ws[warp] = x;
    __syncthreads();
    if (warp == 0) {
        int y = ws[lane];
#pragma unroll
        for (int d = 1; d < 32; d <<= 1) {
            int t = __shfl_up_sync(0xFFFFFFFFu, y, d);
            if (lane >= d) y += t;
        }
        ws[lane] = y;
    }
    __syncthreads();
    return x + (warp > 0 ? ws[warp - 1] : 0);
}
__global__ __launch_bounds__(1024) void scanA(const int* __restrict__ cnt, int* off,
                                              int* bsum, int N) {
    __shared__ int ws[32];
    int i = blockIdx.x * 1024 + threadIdx.x;
    int v = (i < N) ? cnt[i] : 0;
    int incl = block_scan_incl(v, ws);
    if (i < N) off[i] = incl - v;
    if (threadIdx.x == 1023) bsum[blockIdx.x] = incl;
}
__global__ __launch_bounds__(1024) void scanB(int* bsum, int nchunks) {
    __shared__ int ws[32];
    int v = (threadIdx.x < nchunks) ? bsum[threadIdx.x] : 0;
    int incl = block_scan_incl(v, ws);
    if (threadIdx.x < nchunks) bsum[threadIdx.x] = incl - v;
}
// adds block prefix into off; re-materializes cursor into cnt (counts now dead)
__global__ __launch_bounds__(1024) void scanC(int* off, const int* __restrict__ bsum,
                                              int* cursor, int N) {
    int i = blockIdx.x * 1024 + threadIdx.x;
    if (i < N) {
        int o = off[i] + bsum[blockIdx.x];
        off[i] = o;
        cursor[i] = o;
    }
}
__global__ void permute(const int* __restrict__ src, const int* __restrict__ tgt,
                        const int* __restrict__ et, int* cursor,
                        unsigned long long* es, int E) {
    int e = blockIdx.x * blockDim.x + threadIdx.x;
    if (e < E) {
        int s = src[e];
        int pos = atomicAdd(&cursor[s], 1);
        es[pos] = ((unsigned long long)s << 21) | ((unsigned long long)tgt[e] << 4)
                | (unsigned long long)et[e];
    }
}

// ---------------- edge aggregate: one full warp per source node ------------------
__global__ __launch_bounds__(256) void edge_agg(const int* __restrict__ off,
                                                const unsigned long long* __restrict__ es,
                                                const float* __restrict__ coeffs,
                                                const float* __restrict__ p,
                                                float* __restrict__ acc, int N, int E) {
    int g = blockIdx.x * 8 + (threadIdx.x >> 5);
    int lane = threadIdx.x & 31;
    if (g >= N) return;
    int beg = off[g];
    int end = (g + 1 < N) ? off[g + 1] : E;
    if (beg == end) return;

    const float* ps = p + (size_t)g * PCOLS + lane * 2;
    float2 q0 = *(const float2*)(ps);
    float2 q1 = *(const float2*)(ps + 64);
    float2 q2 = *(const float2*)(ps + 128);
    float2 q3 = *(const float2*)(ps + 192);

    unsigned long long e = es[beg];
    for (int i = beg; i < end; i++) {
        unsigned long long enx = (i + 1 < end) ? es[i + 1] : 0ull;
        int t = (int)((e >> 4) & 0x1FFFF);
        int r = (int)(e & 15);
        float4 c = *(const float4*)(coeffs + r * 4);
        float2 m;
        m.x = c.x * q0.x + c.y * q1.x + c.z * q2.x + c.w * q3.x;
        m.y = c.x * q0.y + c.y * q1.y + c.z * q2.y + c.w * q3.y;
        float* dst = acc + (size_t)t * 64 + lane * 2;
        asm volatile("red.global.add.v2.f32 [%0], {%1,%2};"
                     :: "l"(dst), "f"(m.x), "f"(m.y) : "memory");
        e = enx;
    }
}

// ---------------- readout reductions --------------------------------------------
__global__ void zero_stats() {
    int j = threadIdx.x;
    if (j < HDIM) { g_sum[j] = 0.f; g_max[j] = 0; }
}

__global__ __launch_bounds__(256) void reduce_stats(const float* __restrict__ acc, int N) {
    int j = threadIdx.x & 63;
    int rl = threadIdx.x >> 6;
    float s = 0.f, mx = 0.f;
    for (int n = blockIdx.x * 4 + rl; n < N; n += gridDim.x * 4) {
        float v = fmaxf(acc[(size_t)n * 64 + j], 0.f);
        s += v; mx = fmaxf(mx, v);
    }
    __shared__ float ss[4][64];
    __shared__ float smx[4][64];
    ss[rl][j] = s; smx[rl][j] = mx;
    __syncthreads();
    if (rl == 0) {
        s  = ss[0][j] + ss[1][j] + ss[2][j] + ss[3][j];
        mx = fmaxf(fmaxf(smx[0][j], smx[1][j]), fmaxf(smx[2][j], smx[3][j]));
        atomicAdd(&g_sum[j], s);
        atomicMax(&g_max[j], __float_as_int(mx));
    }
}

__global__ void graph_head(const float* __restrict__ Wr1, const float* __restrict__ br1,
                           const float* __restrict__ Wr2, const float* __restrict__ br2,
                           float* __restrict__ out, int N) {
    __shared__ float g[128];
    __shared__ float t[64];
    int tid = threadIdx.x;
    if (tid < 64) g[tid] = g_sum[tid] / (float)N;
    else          g[tid] = __int_as_float(g_max[tid - 64]);
    __syncthreads();
    if (tid < 64) {
        float a = br1[tid];
#pragma unroll 8
        for (int k = 0; k < 128; k++) a += g[k] * Wr1[k * 64 + tid];
        t[tid] = fmaxf(a, 0.f);
    }
    __syncthreads();
    float a = br2[tid];
#pragma unroll 8
    for (int k = 0; k < 64; k++) a += t[k] * Wr2[k * 128 + tid];
    out[tid] = a;
}

// ---------------- launcher -------------------------------------------------------
extern "C" void kernel_launch(void* const* d_in, const int* in_sizes, int n_in,
                              void* d_out, int out_size) {
    const float* x      = (const float*)d_in[0];
    const int*   eidx   = (const int*)  d_in[1];
    const int*   et     = (const int*)  d_in[2];
    const float* Win    = (const float*)d_in[3];
    const float* bin    = (const float*)d_in[4];
    const float* Wself0 = (const float*)d_in[5];
    const float* bself0 = (const float*)d_in[6];
    const float* bases0 = (const float*)d_in[7];
    const float* coef0  = (const float*)d_in[8];
    const float* Wself1 = (const float*)d_in[9];
    const float* bself1 = (const float*)d_in[10];
    const float* bases1 = (const float*)d_in[11];
    const float* coef1  = (const float*)d_in[12];
    const float* Wr1    = (const float*)d_in[13];
    const float* br1    = (const float*)d_in[14];
    const float* Wr2    = (const float*)d_in[15];
    const float* br2    = (const float*)d_in[16];
    const float* Wnp    = (const float*)d_in[17];
    const float* bnp    = (const float*)d_in[18];
    float* out = (float*)d_out;

    int N = in_sizes[0] / 15;
    int E = in_sizes[2];
    const int* src = eidx;
    const int* tgt = eidx + E;

    float *p, *accA, *accB;
    int *cnt, *off, *bsum;
    unsigned long long* es;
    cudaGetSymbolAddress((void**)&p,    g_p);
    cudaGetSymbolAddress((void**)&accA, g_accA);
    cudaGetSymbolAddress((void**)&accB, g_accB);
    cudaGetSymbolAddress((void**)&cnt,  g_cnt);
    cudaGetSymbolAddress((void**)&off,  g_off);
    cudaGetSymbolAddress((void**)&bsum, g_bsum);
    cudaGetSymbolAddress((void**)&es,   g_es);
    float* h0 = accB;          // alias: disjoint lifetimes (see note at globals)
    int* cursor = cnt;         // alias: counts dead after scanA

    cudaFuncSetAttribute(mma_gemm, cudaFuncAttributeMaxDynamicSharedMemorySize, MM_SMEM);

    int agg_blocks = (N + 7) / 8;
    int nchunks    = (N + 1023) / 1024;
    int ntiles     = (N + 127) / 128;

    // ---- sort edges by src (once; shared by both layers) ----
    zero_cnt<<<(N + 1023) / 1024, 1024>>>(cnt, N);
    hist<<<(E + 255) / 256, 256>>>(src, cnt, E);
    scanA<<<nchunks, 1024>>>(cnt, off, bsum, N);
    scanB<<<1, 1024>>>(bsum, nchunks);
    scanC<<<nchunks, 1024>>>(off, bsum, cursor, N);
    permute<<<(E + 255) / 256, 256>>>(src, tgt, et, cursor, es, E);

    // ---- input projection ----
    input_proj<<<(N + 3) / 4, 256>>>(x, Win, bin, h0, N);

    // ---- layer 0: [p | accA] = h0 @ [bases0 | Wself0] (+bself0 on self) ----
    mma_gemm<<<148, 256, MM_SMEM>>>(h0, 0, bases0, 64, 4096, 4, Wself0,
                                    bself0, 0, 64, p, PCOLS, accA, N, ntiles);
    edge_agg<<<agg_blocks, 256>>>(off, es, coef0, p, accA, N, E);

    // ---- layer 1 (input = relu(accA)); accB overwrites h0 (h0 dead) ----
    mma_gemm<<<148, 256, MM_SMEM>>>(accA, 1, bases1, 64, 4096, 4, Wself1,
                                    bself1, 0, 64, p, PCOLS, accB, N, ntiles);
    edge_agg<<<agg_blocks, 256>>>(off, es, coef1, p, accB, N, E);

    // ---- readout (on relu(accB)) ----
    zero_stats<<<1, 64>>>();
    reduce_stats<<<148, 256>>>(accB, N);
    graph_head<<<1, 128>>>(Wr1, br1, Wr2, br2, out, N);

    // ---- node embeddings: out[128 + n*128 + :] = relu(accB) @ Wnp + bnp ----
    mma_gemm<<<148, 256, MM_SMEM>>>(accB, 1, Wnp, 128, 64, 2, nullptr,
                                    bnp, 1, 128, out + 128, 128, nullptr, N, ntiles);
}